// round 16
// baseline (speedup 1.0000x reference)
#include <cuda_runtime.h>
#include <math.h>
#include <stdint.h>

// ---------------- problem constants -----------------------------------------
#define Bq    32
#define NTOK  3136
#define CIN   128
#define CPAD  132
#define Hh    56
#define Wq    56
#define HW    3136
#define HO    28
#define WO    28
#define HWO   784
#define COUT  320
#define NG    196
#define NA    2940
#define SEL   588
#define NOUT  784
#define SORTN 4096
#define KTOT  1152
#define ZH    57
#define ZW    58

// ---------------- scratch (device globals; zero-init at load) ---------------
__device__ float g_feat[Bq * HW * CPAD];               // [b][y][x][c]
__device__ float g_tmp [Bq * HW * CPAD];               // hblur output
__device__ float2 g_zip[(size_t)Bq * ZH * ZW * 128];   // zipped conv input
__device__ float g_fmap[Bq * HWO * COUT];              // conv out, NHWC
// packed {w,w} weights, layout: [(r*10+cblk)*32 + cog*2 + lo], cblk = co>>5
__device__ unsigned long long g_w2[KTOT * COUT];
__device__ float g_S   [Bq * HWO];                     // per-pixel channel sum
__device__ float g_X   [Bq * HWO];                     // per-pixel sum x*(g*w)
__device__ float g_G   [Bq * 29 * 29 * 10];            // per-quad Gram (10 pairs)
__device__ float g_scal[2];                            // {sgw, sbw}
__device__ float g_pert[Bq * NA];
__device__ int   g_idx [Bq * SEL];

// ---------------- Gaussian taps ----------------------------------------------
__device__ __forceinline__ float gw9(int i) {
    const float e0 = 1.0f;
    const float e1 = 0.88249690258459546f;
    const float e2 = 0.60653065971263342f;
    const float e3 = 0.32465246735834974f;
    const float e4 = 0.13533528323661270f;
    const float S  = 1.0f + 2.0f*(e1 + e2 + e3 + e4);
    int d = i - 4; d = d < 0 ? -d : d;
    float e = (d == 0) ? e0 : (d == 1) ? e1 : (d == 2) ? e2 : (d == 3) ? e3 : e4;
    return e / S;
}

// ---------------- packed f32x2 / cp.async helpers -----------------------------
__device__ __forceinline__ void fma2(unsigned long long& d,
                                     unsigned long long a, unsigned long long b) {
    asm("fma.rn.f32x2 %0, %1, %2, %0;" : "+l"(d) : "l"(a), "l"(b));
}
__device__ __forceinline__ float2 unpack2(unsigned long long v) {
    float2 f;
    asm("mov.b64 {%0, %1}, %2;" : "=f"(f.x), "=f"(f.y) : "l"(v));
    return f;
}
__device__ __forceinline__ void cp16(uint32_t dst, const void* src) {
    asm volatile("cp.async.cg.shared.global [%0], [%1], 16;" :: "r"(dst), "l"(src));
}

// ---------------- kernel 1: scatter (+ packed-weight prep in spare blocks) --
__global__ void k_scatter(const float* __restrict__ x, const float* __restrict__ pos,
                          const float* __restrict__ w) {
    int gid = blockIdx.x * 256 + threadIdx.x;
    if (gid < COUT * KTOT) {
        int co = gid / KTOT;          // w layout [co][ci][ky][kx]
        int r  = gid % KTOT;          // r = ci*9 + k
        int cblk = co >> 5;           // 10 blocks of 32 co
        int rem  = co & 31;
        int cog  = rem >> 1;
        int lo   = rem & 1;
        unsigned bits = __float_as_uint(w[gid]);
        unsigned long long u = (unsigned long long)bits | ((unsigned long long)bits << 32);
        g_w2[((size_t)r * 10 + cblk) * 32 + cog * 2 + lo] = u;
    }

    int tok = blockIdx.x * 2 + (threadIdx.x >> 7);
    int c   = threadIdx.x & 127;
    if (tok >= Bq * NTOK) return;
    int b = tok / NTOK;

    float p0 = pos[(size_t)tok * 2 + 0];
    float p1 = pos[(size_t)tok * 2 + 1];
    p0 = fminf(fmaxf(p0, -1.f), 1.f);
    p1 = fminf(fmaxf(p1, -1.f), 1.f);
    int lx = (int)rintf(0.5f * (p0 + 1.0f) * (float)Wq - 0.5f);
    int ly = (int)rintf(0.5f * (p1 + 1.0f) * (float)Hh - 0.5f);
    lx = min(max(lx, 0), Wq - 1);
    ly = min(max(ly, 0), Hh - 1);
    int cell = ly * Wq + lx;

    float* base = g_feat + ((size_t)b * HW + cell) * CPAD;
    atomicAdd(base + c, x[(size_t)tok * CIN + c]);
    if (c == 0) atomicAdd(base + 128, 1.0f);
}

// ---------------- kernel 2: fused normalize + horizontal blur ---------------
__global__ void __launch_bounds__(256) k_blurhn() {
    __shared__ float4 s[64 * 33];
    __shared__ float s_inv[Wq];
    int row = blockIdx.x;                     // over Bq*Hh
    float4* in4  = reinterpret_cast<float4*>(g_feat + (size_t)row * Wq * CPAD);
    float4* out4 = reinterpret_cast<float4*>(g_tmp  + (size_t)row * Wq * CPAD);
    int t = threadIdx.x;

    for (int i = t; i < 64 * 33; i += 256) {
        int c4 = i % 33;
        int xs = i / 33;
        int xm = xs - 4;
        float4 v = make_float4(0.f, 0.f, 0.f, 0.f);
        if ((unsigned)xm < (unsigned)Wq) v = in4[xm * 33 + c4];
        s[i] = v;
    }
    __syncthreads();

    if (t < Wq) {
        float m = s[(t + 4) * 33 + 32].x;
        s_inv[t] = (m > 0.f) ? (1.f / (m + 1e-6f)) : 0.f;
    }
    __syncthreads();

    for (int i = t; i < Wq * 33; i += 256) {
        int c4 = i % 33;
        int x  = i / 33;
        int si = (x + 4) * 33 + c4;
        float4 v = s[si];
        if (c4 < 32) {
            float inv = s_inv[x];
            v.x *= inv; v.y *= inv; v.z *= inv; v.w *= inv;
            s[si] = v;
            in4[i] = v;
        } else {
            v = make_float4(v.x > 0.f ? 1.f : 0.f, 0.f, 0.f, 0.f);
            s[si] = v;
        }
    }
    __syncthreads();

    for (int i = t; i < Wq * 33; i += 256) {
        int c4 = i % 33;
        int x  = i / 33;
        float4 acc = make_float4(0.f, 0.f, 0.f, 0.f);
        #pragma unroll
        for (int k = 0; k < 9; k++) {
            float wk = gw9(k);
            float4 v = s[(x + k) * 33 + c4];
            acc.x += wk * v.x; acc.y += wk * v.y;
            acc.z += wk * v.z; acc.w += wk * v.w;
        }
        out4[i] = acc;
    }
}

// ---------------- kernel 3: vertical blur + hole-fill ------------------------
__global__ void __launch_bounds__(256) k_blurv() {
    __shared__ float s_scale[Wq];
    int blk = blockIdx.x;
    int b = blk / Hh, y = blk % Hh;
    int t = threadIdx.x;

    float wv[9];
    const float* tb[9];
    #pragma unroll
    for (int k = 0; k < 9; k++) {
        int yy = y + k - 4;
        bool ok = (yy >= 0 && yy < Hh);
        wv[k] = ok ? gw9(k) : 0.f;
        int yc = ok ? yy : 0;
        tb[k] = g_tmp + ((size_t)b * HW + yc * Wq) * CPAD;
    }
    const float* fbase = g_feat + ((size_t)b * HW + y * Wq) * CPAD;

    if (t < Wq) {
        float m = fbase[t * CPAD + 128];
        float scale = 0.f;
        if (m <= 0.f) {
            float fm = 0.f;
            #pragma unroll
            for (int k = 0; k < 9; k++) fm += wv[k] * tb[k][t * CPAD + 128];
            scale = (fm > 0.f) ? (1.f / fmaxf(fm, 1e-6f)) : 0.f;
        }
        s_scale[t] = scale;
    }
    __syncthreads();

    for (int i = t; i < Wq * 32; i += 256) {
        int c4 = i % 32;
        int x  = i / 32;
        float sc = s_scale[x];
        if (sc == 0.f) continue;
        float4 fi = make_float4(0.f, 0.f, 0.f, 0.f);
        #pragma unroll
        for (int k = 0; k < 9; k++) {
            float wk = wv[k];
            const float4* p = reinterpret_cast<const float4*>(tb[k] + x * CPAD);
            float4 v = p[c4];
            fi.x += wk * v.x; fi.y += wk * v.y;
            fi.z += wk * v.z; fi.w += wk * v.w;
        }
        float4* fp = reinterpret_cast<float4*>(const_cast<float*>(fbase) + x * CPAD);
        float4 f = fp[c4];
        f.x += fi.x * sc; f.y += fi.y * sc;
        f.z += fi.z * sc; f.w += fi.w * sc;
        fp[c4] = f;
    }
}

// ---------------- kernel 3b: build zipped conv input ------------------------
__global__ void __launch_bounds__(256) k_zip() {
    int blk = blockIdx.x;                    // b*ZH + y'
    int b  = blk / ZH, yp = blk % ZH;
    int y0 = yp - 1, y1 = yp + 1;
    bool v0 = (y0 >= 0);
    bool v1 = (y1 < Hh);
    const float* fb = g_feat + (size_t)b * HW * CPAD;
    float2* zb = g_zip + (size_t)blk * ZW * 128;

    for (int u = threadIdx.x; u < 56 * 32; u += 256) {
        int c4 = u & 31;
        int xp = 1 + (u >> 5);
        int x  = xp - 1;
        float4 va = make_float4(0.f, 0.f, 0.f, 0.f);
        float4 vb = va;
        if (v0) va = *reinterpret_cast<const float4*>(fb + ((size_t)y0 * Wq + x) * CPAD + c4 * 4);
        if (v1) vb = *reinterpret_cast<const float4*>(fb + ((size_t)y1 * Wq + x) * CPAD + c4 * 4);
        float4* d = reinterpret_cast<float4*>(zb + (size_t)xp * 128 + c4 * 4);
        d[0] = make_float4(va.x, vb.x, va.y, vb.y);
        d[1] = make_float4(va.z, vb.z, va.w, vb.w);
    }
}

// ---------------- kernel 4: conv 3x3/s2 128->320, 32-co tiles ----------------
// 2240 blocks of 128 threads; thread = 2 co x 7 px x 2 rows (14 f32x2 accs).
// smem 40.3 KB, low reg pressure -> 4-5 blocks/SM naturally (no forced cap).
#define CI_CHUNK 4
#define NCHUNK  (CIN / CI_CHUNK)
__global__ void __launch_bounds__(128) k_conv(const float* __restrict__ bias) {
    __shared__ __align__(16) float2 s_pack[2][6][57][CI_CHUNK];      // 21,888 B
    __shared__ __align__(16) ulonglong2 s_w2[2][CI_CHUNK][9][16];    // 18,432 B

    int b    = blockIdx.z;
    int oy0  = blockIdx.y * 4;
    int cblk = blockIdx.x;            // co0 = 32*cblk  (0..9)
    int t    = threadIdx.x;
    int co_g = t & 15;                // 2 co each
    int px_g = (t >> 4) & 3;          // 7 px each
    int rp   = t >> 6;                // 0..1 (row pair)

    unsigned long long acc[14];       // [o*7 + sub], o = co offset 0..1
    #pragma unroll
    for (int i = 0; i < 14; i++) acc[i] = 0ull;

    const char* zbase = reinterpret_cast<const char*>(g_zip + (size_t)b * ZH * ZW * 128);
    const ulonglong2* gw2 = reinterpret_cast<const ulonglong2*>(g_w2);

    auto issue = [&](int kc, int buf) {
        int cc = kc * CI_CHUNK;
        for (int u = t; u < 6 * 57; u += 128) {
            int xx = u % 57;
            int pk = u / 57;
            int rp_f = pk / 3, ky = pk - rp_f * 3;
            int yp = 2 * oy0 + 4 * rp_f + ky;            // zip row index
            const char* src = zbase + (((size_t)yp * ZW + xx) * 128 + cc) * 8;
            uint32_t dst = (uint32_t)__cvta_generic_to_shared(&s_pack[buf][pk][xx][0]);
            cp16(dst, src);
            cp16(dst + 16, src + 16);
        }
        // weights: 4ci x 9k x 16 pairs = 576 ulonglong2 units
        for (int i = t; i < CI_CHUNK * 9 * 16; i += 128) {
            int ci  = i / 144;
            int rem = i - ci * 144;
            int k   = rem >> 4;
            int e   = rem & 15;
            const ulonglong2* src = gw2 + ((size_t)((cc + ci) * 9 + k) * 10 + cblk) * 16 + e;
            uint32_t dst = (uint32_t)__cvta_generic_to_shared(&s_w2[buf][0][0][0]) + i * 16;
            cp16(dst, src);
        }
    };

    issue(0, 0);
    asm volatile("cp.async.commit_group;");

    for (int kc = 0; kc < NCHUNK; kc++) {
        int buf = kc & 1;
        if (kc + 1 < NCHUNK) {
            issue(kc + 1, buf ^ 1);
            asm volatile("cp.async.commit_group;");
            asm volatile("cp.async.wait_group 1;");
        } else {
            asm volatile("cp.async.wait_group 0;");
        }
        __syncthreads();

        #pragma unroll
        for (int cip = 0; cip < CI_CHUNK / 2; cip++) {
            #pragma unroll
            for (int ky = 0; ky < 3; ky++) {
                const unsigned long long* au =
                    reinterpret_cast<const unsigned long long*>(
                        &s_pack[buf][rp * 3 + ky][14 * px_g][2 * cip]);
                #pragma unroll
                for (int ch = 0; ch < 2; ch++) {
                    unsigned long long A[15];
                    #pragma unroll
                    for (int j = 0; j < 15; j++) A[j] = au[4 * j + ch];
                    int ci = 2 * cip + ch;
                    #pragma unroll
                    for (int kx = 0; kx < 3; kx++) {
                        ulonglong2 w01 = s_w2[buf][ci][ky * 3 + kx][co_g];
                        #pragma unroll
                        for (int sub = 0; sub < 7; sub++) {
                            unsigned long long a = A[2 * sub + kx];
                            fma2(acc[sub],     a, w01.x);
                            fma2(acc[7 + sub], a, w01.y);
                        }
                    }
                }
            }
        }
        __syncthreads();
    }

    // epilogue: 2 co per thread -> float2 stores (16 threads = 128B contiguous)
    int y0  = oy0 + 2 * rp;
    int co0 = cblk * 32 + co_g * 2;
    size_t base0 = ((size_t)b * HWO + y0 * WO) * COUT + co0;
    float2 b2 = *reinterpret_cast<const float2*>(bias + co0);
    #pragma unroll
    for (int sub = 0; sub < 7; sub++) {
        int px = px_g * 7 + sub;
        float2 f0 = unpack2(acc[sub]);       // co0:   {row y0, row y0+1}
        float2 f1 = unpack2(acc[7 + sub]);   // co0+1: {row y0, row y0+1}
        float2 r0 = make_float2(f0.x + b2.x, f1.x + b2.y);
        float2 r1 = make_float2(f0.y + b2.x, f1.y + b2.y);
        *reinterpret_cast<float2*>(&g_fmap[base0 + (size_t)px * COUT])        = r0;
        *reinterpret_cast<float2*>(&g_fmap[base0 + (size_t)(WO + px) * COUT]) = r1;
    }
}

// ---------------- kernel 5: per-quad Gram + folded per-pixel S/X + scalars --
__global__ void __launch_bounds__(320) k_gram(const float* __restrict__ ln_g,
                                              const float* __restrict__ ln_b,
                                              const float* __restrict__ cw) {
    __shared__ float sc[4][COUT];
    int q  = blockIdx.x;                  // 0..840 (29x29)
    int b  = blockIdx.y;
    int yy = q / 29, xx = q % 29;
    int r0 = max(yy - 1, 0), r1 = min(yy, HO - 1);
    int c0 = max(xx - 1, 0), c1 = min(xx, WO - 1);
    const float* base = g_fmap + (size_t)b * HWO * COUT;
    const float* P[4];
    P[0] = base + (size_t)(r0 * WO + c0) * COUT;
    P[1] = base + (size_t)(r0 * WO + c1) * COUT;
    P[2] = base + (size_t)(r1 * WO + c0) * COUT;
    P[3] = base + (size_t)(r1 * WO + c1) * COUT;

    int t = threadIdx.x;
    #pragma unroll
    for (int k = 0; k < 4; k++) sc[k][t] = P[k][t];
    __syncthreads();

    const int ia[10] = {0,0,0,0,1,1,1,2,2,3};
    const int ib[10] = {0,1,2,3,1,2,3,2,3,3};
    int w    = t >> 5;                    // pair id 0..9
    int lane = t & 31;
    const float* pa = sc[ia[w]];
    const float* pb = sc[ib[w]];

    float d = 0.f;
    if (w == 0) {
        float s = 0.f, xw = 0.f;
        #pragma unroll
        for (int c = lane; c < COUT; c += 32) {
            float v = pa[c];
            d  += v * v;
            s  += v;
            xw += v * (ln_g[c] * cw[c]);
        }
        #pragma unroll
        for (int o = 16; o > 0; o >>= 1) {
            d  += __shfl_xor_sync(0xffffffffu, d,  o);
            s  += __shfl_xor_sync(0xffffffffu, s,  o);
            xw += __shfl_xor_sync(0xffffffffu, xw, o);
        }
        if (lane == 0) {
            int pix = b * HWO + r0 * WO + c0;
            g_S[pix] = s;
            g_X[pix] = xw;
        }
    } else {
        #pragma unroll
        for (int c = lane; c < COUT; c += 32) d += pa[c] * pb[c];
        #pragma unroll
        for (int o = 16; o > 0; o >>= 1) d += __shfl_xor_sync(0xffffffffu, d, o);
    }
    if (lane == 0) g_G[((size_t)b * 841 + q) * 10 + w] = d;

    if (w == 1 && q == 0 && b == 0) {
        float sgw = 0.f, sbw = 0.f;
        #pragma unroll
        for (int c = lane; c < COUT; c += 32) {
            float wc = cw[c];
            sgw += ln_g[c] * wc;
            sbw += ln_b[c] * wc;
        }
        #pragma unroll
        for (int o = 16; o > 0; o >>= 1) {
            sgw += __shfl_xor_sync(0xffffffffu, sgw, o);
            sbw += __shfl_xor_sync(0xffffffffu, sbw, o);
        }
        if (lane == 0) { g_scal[0] = sgw; g_scal[1] = sbw; }
    }
}

// ---------------- kernel 5c: conf via Gram (thread per token) ----------------
__global__ void __launch_bounds__(256) k_conf(const float* __restrict__ pos,
                                              const float* __restrict__ cb,
                                              const float* __restrict__ noise) {
    int id = blockIdx.x * blockDim.x + threadIdx.x;
    if (id >= Bq * NA) return;
    int b = id / NA;
    int j = id % NA;
    int n = NG + j;

    float p0 = pos[((size_t)b * NTOK + n) * 2 + 0];
    float p1 = pos[((size_t)b * NTOK + n) * 2 + 1];
    float gx = ((p0 + 1.f) * (float)WO - 1.f) * 0.5f;
    float gy = ((p1 + 1.f) * (float)HO - 1.f) * 0.5f;
    float x0f = floorf(gx), y0f = floorf(gy);
    float wx = gx - x0f, wy = gy - y0f;
    int x0 = (int)x0f, y0 = (int)y0f;
    int x1 = x0 + 1,   y1 = y0 + 1;

    bool i00 = (x0 >= 0) && (y0 >= 0);
    bool i01 = (x1 < WO) && (y0 >= 0);
    bool i10 = (x0 >= 0) && (y1 < HO);
    bool i11 = (x1 < WO) && (y1 < HO);
    float w0 = i00 ? (1.f - wx) * (1.f - wy) : 0.f;
    float w1 = i01 ? wx * (1.f - wy)         : 0.f;
    float w2 = i10 ? (1.f - wx) * wy         : 0.f;
    float w3 = i11 ? wx * wy                 : 0.f;

    int c0 = max(x0, 0), c1 = min(x1, WO - 1);
    int r0 = max(y0, 0), r1 = min(y1, HO - 1);
    int pbase = b * HWO;
    int q00 = pbase + r0 * WO + c0;
    int q01 = pbase + r0 * WO + c1;
    int q10 = pbase + r1 * WO + c0;
    int q11 = pbase + r1 * WO + c1;

    float s1  = w0 * g_S[q00] + w1 * g_S[q01] + w2 * g_S[q10] + w3 * g_S[q11];
    float sxw = w0 * g_X[q00] + w1 * g_X[q01] + w2 * g_X[q10] + w3 * g_X[q11];

    const float* G = &g_G[((size_t)b * 841 + (y0 + 1) * 29 + (x0 + 1)) * 10];
    float s2 = w0 * w0 * G[0] + w1 * w1 * G[4] + w2 * w2 * G[7] + w3 * w3 * G[9]
             + 2.f * (w0 * w1 * G[1] + w0 * w2 * G[2] + w0 * w3 * G[3]
                    + w1 * w2 * G[5] + w1 * w3 * G[6] + w2 * w3 * G[8]);

    float mu  = s1 * (1.f / (float)COUT);
    float var = s2 * (1.f / (float)COUT) - mu * mu;
    float rs  = rsqrtf(var + 1e-5f);
    float conf = rs * (sxw - mu * g_scal[0]) + g_scal[1] + cb[0];
    float nz = noise[(size_t)b * NA + j];
    float g  = -logf(-logf(nz + 1e-6f) + 1e-6f);
    g_pert[id] = conf + g;
}

// ---------------- kernel 6: per-batch top-k via bitonic sort -----------------
__global__ void __launch_bounds__(1024) k_sort() {
    __shared__ unsigned long long s[SORTN];
    int b = blockIdx.x;
    int t = threadIdx.x;

    for (int i = t; i < SORTN; i += 1024) {
        unsigned long long key;
        if (i < NA) {
            float v = g_pert[b * NA + i];
            unsigned u = __float_as_uint(v);
            u = (u & 0x80000000u) ? ~u : (u | 0x80000000u);
            key = (((unsigned long long)(~u)) << 32) | (unsigned)i;
        } else {
            key = 0xFFFFFFFFFFFFFFFFull;
        }
        s[i] = key;
    }
    __syncthreads();

    for (int k = 2; k <= SORTN; k <<= 1) {
        for (int jj = k >> 1; jj > 0; jj >>= 1) {
            for (int i = t; i < SORTN; i += 1024) {
                int l = i ^ jj;
                if (l > i) {
                    unsigned long long a = s[i], c = s[l];
                    bool up = ((i & k) == 0);
                    if ((a > c) == up) { s[i] = c; s[l] = a; }
                }
            }
            __syncthreads();
        }
    }
    for (int i = t; i < SEL; i += 1024)
        g_idx[b * SEL + i] = (int)(unsigned)(s[i] & 0xFFFFFFFFull);
}

// ---------------- bilinear helper (fmap NHWC 28x28x320) ----------------------
struct Bilin { float w0, w1, w2, w3; const float *p0, *p1, *p2, *p3; };

__device__ __forceinline__ Bilin bilin_setup(int b, float px, float py) {
    float gx = ((px + 1.f) * (float)WO - 1.f) * 0.5f;
    float gy = ((py + 1.f) * (float)HO - 1.f) * 0.5f;
    float x0f = floorf(gx), y0f = floorf(gy);
    float wx = gx - x0f, wy = gy - y0f;
    int x0 = (int)x0f, y0 = (int)y0f;
    int x1 = x0 + 1,   y1 = y0 + 1;

    bool i00 = (x0 >= 0 && x0 < WO && y0 >= 0 && y0 < HO);
    bool i01 = (x1 >= 0 && x1 < WO && y0 >= 0 && y0 < HO);
    bool i10 = (x0 >= 0 && x0 < WO && y1 >= 0 && y1 < HO);
    bool i11 = (x1 >= 0 && x1 < WO && y1 >= 0 && y1 < HO);
    int x0c = min(max(x0, 0), WO - 1), x1c = min(max(x1, 0), WO - 1);
    int y0c = min(max(y0, 0), HO - 1), y1c = min(max(y1, 0), HO - 1);

    Bilin r;
    r.w0 = i00 ? (1.f - wx) * (1.f - wy) : 0.f;
    r.w1 = i01 ? wx * (1.f - wy)         : 0.f;
    r.w2 = i10 ? (1.f - wx) * wy         : 0.f;
    r.w3 = i11 ? wx * wy                 : 0.f;
    const float* base = g_fmap + (size_t)b * HWO * COUT;
    r.p0 = base + (size_t)(y0c * WO + x0c) * COUT;
    r.p1 = base + (size_t)(y0c * WO + x1c) * COUT;
    r.p2 = base + (size_t)(y1c * WO + x0c) * COUT;
    r.p3 = base + (size_t)(y1c * WO + x1c) * COUT;
    return r;
}

// ---------------- kernel 7: gather output + fold in g_feat zeroing -----------
__global__ void __launch_bounds__(320) k_gather(const float* __restrict__ pos,
                                                float* __restrict__ out) {
    {
        int zi = blockIdx.x * 320 + threadIdx.x;
        const int n4 = (Bq * HW * CPAD) / 4;
        if (zi < n4)
            reinterpret_cast<float4*>(g_feat)[zi] = make_float4(0.f, 0.f, 0.f, 0.f);
    }

    int tok = blockIdx.x;
    int b = tok / NOUT, j = tok % NOUT;
    int n = (j < NG) ? j : (NG + g_idx[b * SEL + (j - NG)]);

    float p0 = pos[((size_t)b * NTOK + n) * 2 + 0];
    float p1 = pos[((size_t)b * NTOK + n) * 2 + 1];
    Bilin bl = bilin_setup(b, p0, p1);

    int c = threadIdx.x;
    float xc = bl.w0 * bl.p0[c] + bl.w1 * bl.p1[c]
             + bl.w2 * bl.p2[c] + bl.w3 * bl.p3[c];
    out[(size_t)tok * COUT + c] = xc;

    if (c < 2) {
        float* po = out + (size_t)Bq * NOUT * COUT + (size_t)tok * 2;
        po[c] = (c == 0) ? p0 : p1;
    }
}

// ---------------- launcher ----------------------------------------------------
extern "C" void kernel_launch(void* const* d_in, const int* in_sizes, int n_in,
                              void* d_out, int out_size) {
    const float* x      = (const float*)d_in[0];
    const float* pos    = (const float*)d_in[1];
    const float* conv_w = (const float*)d_in[2];
    const float* conv_b = (const float*)d_in[3];
    const float* ln_g   = (const float*)d_in[4];
    const float* ln_b   = (const float*)d_in[5];
    const float* conf_w = (const float*)d_in[6];
    const float* conf_b = (const float*)d_in[7];
    const float* noise  = (const float*)d_in[8];
    float* out = (float*)d_out;

    // precondition: g_feat is zero (module-load init on first call; gather re-zeros)
    k_scatter<<<(Bq * NTOK + 1) / 2, 256>>>(x, pos, conv_w);  // #1
    k_blurhn<<<Bq * Hh, 256>>>();                             // #2
    k_blurv<<<Bq * Hh, 256>>>();                              // #3
    k_zip<<<Bq * ZH, 256>>>();                                // #4

    dim3 cgrid(COUT / 32, HO / 4, Bq);                        // (10, 7, 32)
    k_conv<<<cgrid, 128>>>(conv_b);                           // #5

    {
        dim3 ggrid(29 * 29, Bq);
        k_gram<<<ggrid, 320>>>(ln_g, ln_b, conf_w);           // #6 (+pix fold)
    }
    k_conf<<<(Bq * NA + 255) / 256, 256>>>(pos, conf_b, noise); // #7
    k_sort<<<Bq, 1024>>>();                                   // #8
    k_gather<<<Bq * NOUT, 320>>>(pos, out);                   // #9 (+zero fold)
}

// round 17
// speedup vs baseline: 1.0895x; 1.0895x over previous
#include <cuda_runtime.h>
#include <math.h>
#include <stdint.h>

// ---------------- problem constants -----------------------------------------
#define Bq    32
#define NTOK  3136
#define CIN   128
#define CPAD  132
#define Hh    56
#define Wq    56
#define HW    3136
#define HO    28
#define WO    28
#define HWO   784
#define COUT  320
#define NG    196
#define NA    2940
#define SEL   588
#define NOUT  784
#define SORTN 4096
#define KTOT  1152
#define ZH    57
#define ZW    58

// ---------------- scratch (device globals; zero-init at load) ---------------
__device__ float g_feat[Bq * HW * CPAD];               // [b][y][x][c]
__device__ float g_tmp [Bq * HW * CPAD];               // hblur output
__device__ float2 g_zip[(size_t)Bq * ZH * ZW * 128];   // zipped conv input
__device__ float g_fmap[Bq * HWO * COUT];              // conv out, NHWC
// packed {w,w} weights, layout: [(r*5+cblk)*64 + (p*16+cog)*2 + lo]
__device__ unsigned long long g_w2[KTOT * COUT];
__device__ float g_S   [Bq * HWO];                     // per-pixel channel sum
__device__ float g_X   [Bq * HWO];                     // per-pixel sum x*(g*w)
__device__ float g_G   [Bq * 29 * 29 * 10];            // per-quad Gram (10 pairs)
__device__ float g_scal[2];                            // {sgw, sbw}
__device__ float g_pert[Bq * NA];
__device__ int   g_idx [Bq * SEL];

// ---------------- Gaussian taps ----------------------------------------------
__device__ __forceinline__ float gw9(int i) {
    const float e0 = 1.0f;
    const float e1 = 0.88249690258459546f;
    const float e2 = 0.60653065971263342f;
    const float e3 = 0.32465246735834974f;
    const float e4 = 0.13533528323661270f;
    const float S  = 1.0f + 2.0f*(e1 + e2 + e3 + e4);
    int d = i - 4; d = d < 0 ? -d : d;
    float e = (d == 0) ? e0 : (d == 1) ? e1 : (d == 2) ? e2 : (d == 3) ? e3 : e4;
    return e / S;
}

// ---------------- packed f32x2 / cp.async helpers -----------------------------
__device__ __forceinline__ void fma2(unsigned long long& d,
                                     unsigned long long a, unsigned long long b) {
    asm("fma.rn.f32x2 %0, %1, %2, %0;" : "+l"(d) : "l"(a), "l"(b));
}
__device__ __forceinline__ float2 unpack2(unsigned long long v) {
    float2 f;
    asm("mov.b64 {%0, %1}, %2;" : "=f"(f.x), "=f"(f.y) : "l"(v));
    return f;
}
__device__ __forceinline__ void cp16(uint32_t dst, const void* src) {
    asm volatile("cp.async.cg.shared.global [%0], [%1], 16;" :: "r"(dst), "l"(src));
}

// ---------------- kernel 1: scatter, float4 atomics (+ weight pack) ---------
// 8 tokens per 256-thread block; 32 threads/token, one RED.128 per thread.
__global__ void k_scatter(const float* __restrict__ x, const float* __restrict__ pos,
                          const float* __restrict__ w) {
    int gid = blockIdx.x * 256 + threadIdx.x;
    if (gid < COUT * KTOT) {
        int co = gid / KTOT;          // w layout [co][ci][ky][kx]
        int r  = gid % KTOT;          // r = ci*9 + k
        int cblk = co >> 6;
        int rem  = co & 63;
        int cog  = rem >> 2;
        int p    = (rem >> 1) & 1;
        int lo   = rem & 1;
        unsigned bits = __float_as_uint(w[gid]);
        unsigned long long u = (unsigned long long)bits | ((unsigned long long)bits << 32);
        g_w2[((size_t)r * 5 + cblk) * 64 + (p * 16 + cog) * 2 + lo] = u;
    }

    int tok = blockIdx.x * 8 + (threadIdx.x >> 5);
    int c4  = threadIdx.x & 31;
    if (tok >= Bq * NTOK) return;
    int b = tok / NTOK;

    float p0 = pos[(size_t)tok * 2 + 0];
    float p1 = pos[(size_t)tok * 2 + 1];
    p0 = fminf(fmaxf(p0, -1.f), 1.f);
    p1 = fminf(fmaxf(p1, -1.f), 1.f);
    int lx = (int)rintf(0.5f * (p0 + 1.0f) * (float)Wq - 0.5f);
    int ly = (int)rintf(0.5f * (p1 + 1.0f) * (float)Hh - 0.5f);
    lx = min(max(lx, 0), Wq - 1);
    ly = min(max(ly, 0), Hh - 1);
    int cell = ly * Wq + lx;

    float* base = g_feat + ((size_t)b * HW + cell) * CPAD;
    float4 xv = reinterpret_cast<const float4*>(x + (size_t)tok * CIN)[c4];
    atomicAdd(reinterpret_cast<float4*>(base) + c4, xv);
    if (c4 == 0) atomicAdd(base + 128, 1.0f);
}

// ---------------- kernel 2: fused normalize + horizontal blur ---------------
__global__ void __launch_bounds__(256) k_blurhn() {
    __shared__ float4 s[64 * 33];
    __shared__ float s_inv[Wq];
    int row = blockIdx.x;                     // over Bq*Hh
    float4* in4  = reinterpret_cast<float4*>(g_feat + (size_t)row * Wq * CPAD);
    float4* out4 = reinterpret_cast<float4*>(g_tmp  + (size_t)row * Wq * CPAD);
    int t = threadIdx.x;

    for (int i = t; i < 64 * 33; i += 256) {
        int c4 = i % 33;
        int xs = i / 33;
        int xm = xs - 4;
        float4 v = make_float4(0.f, 0.f, 0.f, 0.f);
        if ((unsigned)xm < (unsigned)Wq) v = in4[xm * 33 + c4];
        s[i] = v;
    }
    __syncthreads();

    if (t < Wq) {
        float m = s[(t + 4) * 33 + 32].x;
        s_inv[t] = (m > 0.f) ? (1.f / (m + 1e-6f)) : 0.f;
    }
    __syncthreads();

    for (int i = t; i < Wq * 33; i += 256) {
        int c4 = i % 33;
        int x  = i / 33;
        int si = (x + 4) * 33 + c4;
        float4 v = s[si];
        if (c4 < 32) {
            float inv = s_inv[x];
            v.x *= inv; v.y *= inv; v.z *= inv; v.w *= inv;
            s[si] = v;
            in4[i] = v;
        } else {
            v = make_float4(v.x > 0.f ? 1.f : 0.f, 0.f, 0.f, 0.f);
            s[si] = v;
        }
    }
    __syncthreads();

    for (int i = t; i < Wq * 33; i += 256) {
        int c4 = i % 33;
        int x  = i / 33;
        float4 acc = make_float4(0.f, 0.f, 0.f, 0.f);
        #pragma unroll
        for (int k = 0; k < 9; k++) {
            float wk = gw9(k);
            float4 v = s[(x + k) * 33 + c4];
            acc.x += wk * v.x; acc.y += wk * v.y;
            acc.z += wk * v.z; acc.w += wk * v.w;
        }
        out4[i] = acc;
    }
}

// ---------------- kernel 3: vertical blur + hole-fill ------------------------
__global__ void __launch_bounds__(256) k_blurv() {
    __shared__ float s_scale[Wq];
    int blk = blockIdx.x;
    int b = blk / Hh, y = blk % Hh;
    int t = threadIdx.x;

    float wv[9];
    const float* tb[9];
    #pragma unroll
    for (int k = 0; k < 9; k++) {
        int yy = y + k - 4;
        bool ok = (yy >= 0 && yy < Hh);
        wv[k] = ok ? gw9(k) : 0.f;
        int yc = ok ? yy : 0;
        tb[k] = g_tmp + ((size_t)b * HW + yc * Wq) * CPAD;
    }
    const float* fbase = g_feat + ((size_t)b * HW + y * Wq) * CPAD;

    if (t < Wq) {
        float m = fbase[t * CPAD + 128];
        float scale = 0.f;
        if (m <= 0.f) {
            float fm = 0.f;
            #pragma unroll
            for (int k = 0; k < 9; k++) fm += wv[k] * tb[k][t * CPAD + 128];
            scale = (fm > 0.f) ? (1.f / fmaxf(fm, 1e-6f)) : 0.f;
        }
        s_scale[t] = scale;
    }
    __syncthreads();

    for (int i = t; i < Wq * 32; i += 256) {
        int c4 = i % 32;
        int x  = i / 32;
        float sc = s_scale[x];
        if (sc == 0.f) continue;
        float4 fi = make_float4(0.f, 0.f, 0.f, 0.f);
        #pragma unroll
        for (int k = 0; k < 9; k++) {
            float wk = wv[k];
            const float4* p = reinterpret_cast<const float4*>(tb[k] + x * CPAD);
            float4 v = p[c4];
            fi.x += wk * v.x; fi.y += wk * v.y;
            fi.z += wk * v.z; fi.w += wk * v.w;
        }
        float4* fp = reinterpret_cast<float4*>(const_cast<float*>(fbase) + x * CPAD);
        float4 f = fp[c4];
        f.x += fi.x * sc; f.y += fi.y * sc;
        f.z += fi.z * sc; f.w += fi.w * sc;
        fp[c4] = f;
    }
}

// ---------------- kernel 3b: build zipped conv input ------------------------
__global__ void __launch_bounds__(256) k_zip() {
    int blk = blockIdx.x;                    // b*ZH + y'
    int b  = blk / ZH, yp = blk % ZH;
    int y0 = yp - 1, y1 = yp + 1;
    bool v0 = (y0 >= 0);
    bool v1 = (y1 < Hh);
    const float* fb = g_feat + (size_t)b * HW * CPAD;
    float2* zb = g_zip + (size_t)blk * ZW * 128;

    for (int u = threadIdx.x; u < 56 * 32; u += 256) {
        int c4 = u & 31;
        int xp = 1 + (u >> 5);
        int x  = xp - 1;
        float4 va = make_float4(0.f, 0.f, 0.f, 0.f);
        float4 vb = va;
        if (v0) va = *reinterpret_cast<const float4*>(fb + ((size_t)y0 * Wq + x) * CPAD + c4 * 4);
        if (v1) vb = *reinterpret_cast<const float4*>(fb + ((size_t)y1 * Wq + x) * CPAD + c4 * 4);
        float4* d = reinterpret_cast<float4*>(zb + (size_t)xp * 128 + c4 * 4);
        d[0] = make_float4(va.x, vb.x, va.y, vb.y);
        d[1] = make_float4(va.z, vb.z, va.w, vb.w);
    }
}

// ---------------- kernel 4: conv 3x3/s2 128->320 (R8/R15 pipeline) ----------
#define CI_CHUNK 4
#define NCHUNK  (CIN / CI_CHUNK)
__global__ void __launch_bounds__(128) k_conv(const float* __restrict__ bias) {
    __shared__ __align__(16) float2 s_pack[2][6][57][CI_CHUNK];          // 21,888 B
    __shared__ __align__(16) ulonglong2 s_w2[2][CI_CHUNK][9][2][16];     // 36,864 B

    int b    = blockIdx.z;
    int oy0  = blockIdx.y * 4;
    int cblk = blockIdx.x;            // co0 = 64*cblk
    int t    = threadIdx.x;
    int co_g = t & 15;                // 4 co each
    int px_g = (t >> 4) & 3;          // 7 px each
    int rp   = t >> 6;                // 0..1 (row pair)

    unsigned long long acc[28];       // [o*7 + sub]
    #pragma unroll
    for (int i = 0; i < 28; i++) acc[i] = 0ull;

    const char* zbase = reinterpret_cast<const char*>(g_zip + (size_t)b * ZH * ZW * 128);
    const char* wbase = reinterpret_cast<const char*>(g_w2);

    auto issue = [&](int kc, int buf) {
        int cc = kc * CI_CHUNK;
        for (int u = t; u < 6 * 57; u += 128) {
            int xx = u % 57;
            int pk = u / 57;
            int rp_f = pk / 3, ky = pk - rp_f * 3;
            int yp = 2 * oy0 + 4 * rp_f + ky;            // zip row index
            const char* src = zbase + (((size_t)yp * ZW + xx) * 128 + cc) * 8;
            uint32_t dst = (uint32_t)__cvta_generic_to_shared(&s_pack[buf][pk][xx][0]);
            cp16(dst, src);
            cp16(dst + 16, src + 16);
        }
        for (int i = t; i < CI_CHUNK * 9 * 32; i += 128) {
            int ci  = i / 288;
            int rem = i - ci * 288;
            int k   = rem >> 5;
            int e   = rem & 31;
            const char* src = wbase + ((((size_t)(cc + ci) * 9 + k) * 5 + cblk) * 64) * 8 + e * 16;
            uint32_t dst = (uint32_t)__cvta_generic_to_shared(
                reinterpret_cast<char*>(&s_w2[buf][ci][k][0][0]) + e * 16);
            cp16(dst, src);
        }
    };

    issue(0, 0);
    asm volatile("cp.async.commit_group;");

    for (int kc = 0; kc < NCHUNK; kc++) {
        int buf = kc & 1;
        if (kc + 1 < NCHUNK) {
            issue(kc + 1, buf ^ 1);
            asm volatile("cp.async.commit_group;");
            asm volatile("cp.async.wait_group 1;");
        } else {
            asm volatile("cp.async.wait_group 0;");
        }
        __syncthreads();

        #pragma unroll
        for (int cip = 0; cip < CI_CHUNK / 2; cip++) {
            #pragma unroll
            for (int ky = 0; ky < 3; ky++) {
                const unsigned long long* au =
                    reinterpret_cast<const unsigned long long*>(
                        &s_pack[buf][rp * 3 + ky][14 * px_g][2 * cip]);
                #pragma unroll
                for (int ch = 0; ch < 2; ch++) {
                    unsigned long long A[15];
                    #pragma unroll
                    for (int j = 0; j < 15; j++) A[j] = au[4 * j + ch];
                    int ci = 2 * cip + ch;
                    #pragma unroll
                    for (int kx = 0; kx < 3; kx++) {
                        ulonglong2 w01 = s_w2[buf][ci][ky * 3 + kx][0][co_g];
                        ulonglong2 w23 = s_w2[buf][ci][ky * 3 + kx][1][co_g];
                        #pragma unroll
                        for (int sub = 0; sub < 7; sub++) {
                            unsigned long long a = A[2 * sub + kx];
                            fma2(acc[sub],      a, w01.x);
                            fma2(acc[7 + sub],  a, w01.y);
                            fma2(acc[14 + sub], a, w23.x);
                            fma2(acc[21 + sub], a, w23.y);
                        }
                    }
                }
            }
        }
        __syncthreads();
    }

    int y0  = oy0 + 2 * rp;
    int co0 = cblk * 64 + co_g * 4;
    size_t base0 = ((size_t)b * HWO + y0 * WO) * COUT + co0;
    float4 b4 = *reinterpret_cast<const float4*>(bias + co0);
    #pragma unroll
    for (int sub = 0; sub < 7; sub++) {
        int px = px_g * 7 + sub;
        float2 f0 = unpack2(acc[sub]);
        float2 f1 = unpack2(acc[7 + sub]);
        float2 f2 = unpack2(acc[14 + sub]);
        float2 f3 = unpack2(acc[21 + sub]);
        float4 r0 = make_float4(f0.x + b4.x, f1.x + b4.y, f2.x + b4.z, f3.x + b4.w);
        float4 r1 = make_float4(f0.y + b4.x, f1.y + b4.y, f2.y + b4.z, f3.y + b4.w);
        *reinterpret_cast<float4*>(&g_fmap[base0 + (size_t)px * COUT])        = r0;
        *reinterpret_cast<float4*>(&g_fmap[base0 + (size_t)(WO + px) * COUT]) = r1;
    }
}

// ---------------- kernel 5: per-quad Gram + folded per-pixel S/X + scalars --
__global__ void __launch_bounds__(320) k_gram(const float* __restrict__ ln_g,
                                              const float* __restrict__ ln_b,
                                              const float* __restrict__ cw) {
    __shared__ float sc[4][COUT];
    int q  = blockIdx.x;                  // 0..840 (29x29)
    int b  = blockIdx.y;
    int yy = q / 29, xx = q % 29;
    int r0 = max(yy - 1, 0), r1 = min(yy, HO - 1);
    int c0 = max(xx - 1, 0), c1 = min(xx, WO - 1);
    const float* base = g_fmap + (size_t)b * HWO * COUT;
    const float* P[4];
    P[0] = base + (size_t)(r0 * WO + c0) * COUT;
    P[1] = base + (size_t)(r0 * WO + c1) * COUT;
    P[2] = base + (size_t)(r1 * WO + c0) * COUT;
    P[3] = base + (size_t)(r1 * WO + c1) * COUT;

    int t = threadIdx.x;
    #pragma unroll
    for (int k = 0; k < 4; k++) sc[k][t] = P[k][t];
    __syncthreads();

    const int ia[10] = {0,0,0,0,1,1,1,2,2,3};
    const int ib[10] = {0,1,2,3,1,2,3,2,3,3};
    int w    = t >> 5;                    // pair id 0..9
    int lane = t & 31;
    const float* pa = sc[ia[w]];
    const float* pb = sc[ib[w]];

    float d = 0.f;
    if (w == 0) {
        float s = 0.f, xw = 0.f;
        #pragma unroll
        for (int c = lane; c < COUT; c += 32) {
            float v = pa[c];
            d  += v * v;
            s  += v;
            xw += v * (ln_g[c] * cw[c]);
        }
        #pragma unroll
        for (int o = 16; o > 0; o >>= 1) {
            d  += __shfl_xor_sync(0xffffffffu, d,  o);
            s  += __shfl_xor_sync(0xffffffffu, s,  o);
            xw += __shfl_xor_sync(0xffffffffu, xw, o);
        }
        if (lane == 0) {
            int pix = b * HWO + r0 * WO + c0;
            g_S[pix] = s;
            g_X[pix] = xw;
        }
    } else {
        #pragma unroll
        for (int c = lane; c < COUT; c += 32) d += pa[c] * pb[c];
        #pragma unroll
        for (int o = 16; o > 0; o >>= 1) d += __shfl_xor_sync(0xffffffffu, d, o);
    }
    if (lane == 0) g_G[((size_t)b * 841 + q) * 10 + w] = d;

    if (w == 1 && q == 0 && b == 0) {
        float sgw = 0.f, sbw = 0.f;
        #pragma unroll
        for (int c = lane; c < COUT; c += 32) {
            float wc = cw[c];
            sgw += ln_g[c] * wc;
            sbw += ln_b[c] * wc;
        }
        #pragma unroll
        for (int o = 16; o > 0; o >>= 1) {
            sgw += __shfl_xor_sync(0xffffffffu, sgw, o);
            sbw += __shfl_xor_sync(0xffffffffu, sbw, o);
        }
        if (lane == 0) { g_scal[0] = sgw; g_scal[1] = sbw; }
    }
}

// ---------------- kernel 5c: conf via Gram (thread per token) ----------------
__global__ void __launch_bounds__(256) k_conf(const float* __restrict__ pos,
                                              const float* __restrict__ cb,
                                              const float* __restrict__ noise) {
    int id = blockIdx.x * blockDim.x + threadIdx.x;
    if (id >= Bq * NA) return;
    int b = id / NA;
    int j = id % NA;
    int n = NG + j;

    float p0 = pos[((size_t)b * NTOK + n) * 2 + 0];
    float p1 = pos[((size_t)b * NTOK + n) * 2 + 1];
    float gx = ((p0 + 1.f) * (float)WO - 1.f) * 0.5f;
    float gy = ((p1 + 1.f) * (float)HO - 1.f) * 0.5f;
    float x0f = floorf(gx), y0f = floorf(gy);
    float wx = gx - x0f, wy = gy - y0f;
    int x0 = (int)x0f, y0 = (int)y0f;
    int x1 = x0 + 1,   y1 = y0 + 1;

    bool i00 = (x0 >= 0) && (y0 >= 0);
    bool i01 = (x1 < WO) && (y0 >= 0);
    bool i10 = (x0 >= 0) && (y1 < HO);
    bool i11 = (x1 < WO) && (y1 < HO);
    float w0 = i00 ? (1.f - wx) * (1.f - wy) : 0.f;
    float w1 = i01 ? wx * (1.f - wy)         : 0.f;
    float w2 = i10 ? (1.f - wx) * wy         : 0.f;
    float w3 = i11 ? wx * wy                 : 0.f;

    int c0 = max(x0, 0), c1 = min(x1, WO - 1);
    int r0 = max(y0, 0), r1 = min(y1, HO - 1);
    int pbase = b * HWO;
    int q00 = pbase + r0 * WO + c0;
    int q01 = pbase + r0 * WO + c1;
    int q10 = pbase + r1 * WO + c0;
    int q11 = pbase + r1 * WO + c1;

    float s1  = w0 * g_S[q00] + w1 * g_S[q01] + w2 * g_S[q10] + w3 * g_S[q11];
    float sxw = w0 * g_X[q00] + w1 * g_X[q01] + w2 * g_X[q10] + w3 * g_X[q11];

    const float* G = &g_G[((size_t)b * 841 + (y0 + 1) * 29 + (x0 + 1)) * 10];
    float s2 = w0 * w0 * G[0] + w1 * w1 * G[4] + w2 * w2 * G[7] + w3 * w3 * G[9]
             + 2.f * (w0 * w1 * G[1] + w0 * w2 * G[2] + w0 * w3 * G[3]
                    + w1 * w2 * G[5] + w1 * w3 * G[6] + w2 * w3 * G[8]);

    float mu  = s1 * (1.f / (float)COUT);
    float var = s2 * (1.f / (float)COUT) - mu * mu;
    float rs  = rsqrtf(var + 1e-5f);
    float conf = rs * (sxw - mu * g_scal[0]) + g_scal[1] + cb[0];
    float nz = noise[(size_t)b * NA + j];
    float g  = -logf(-logf(nz + 1e-6f) + 1e-6f);
    g_pert[id] = conf + g;
}

// ---------------- kernel 6: per-batch top-k via bitonic sort -----------------
__global__ void __launch_bounds__(1024) k_sort() {
    __shared__ unsigned long long s[SORTN];
    int b = blockIdx.x;
    int t = threadIdx.x;

    for (int i = t; i < SORTN; i += 1024) {
        unsigned long long key;
        if (i < NA) {
            float v = g_pert[b * NA + i];
            unsigned u = __float_as_uint(v);
            u = (u & 0x80000000u) ? ~u : (u | 0x80000000u);
            key = (((unsigned long long)(~u)) << 32) | (unsigned)i;
        } else {
            key = 0xFFFFFFFFFFFFFFFFull;
        }
        s[i] = key;
    }
    __syncthreads();

    for (int k = 2; k <= SORTN; k <<= 1) {
        for (int jj = k >> 1; jj > 0; jj >>= 1) {
            for (int i = t; i < SORTN; i += 1024) {
                int l = i ^ jj;
                if (l > i) {
                    unsigned long long a = s[i], c = s[l];
                    bool up = ((i & k) == 0);
                    if ((a > c) == up) { s[i] = c; s[l] = a; }
                }
            }
            __syncthreads();
        }
    }
    for (int i = t; i < SEL; i += 1024)
        g_idx[b * SEL + i] = (int)(unsigned)(s[i] & 0xFFFFFFFFull);
}

// ---------------- bilinear helper (fmap NHWC 28x28x320) ----------------------
struct Bilin { float w0, w1, w2, w3; const float *p0, *p1, *p2, *p3; };

__device__ __forceinline__ Bilin bilin_setup(int b, float px, float py) {
    float gx = ((px + 1.f) * (float)WO - 1.f) * 0.5f;
    float gy = ((py + 1.f) * (float)HO - 1.f) * 0.5f;
    float x0f = floorf(gx), y0f = floorf(gy);
    float wx = gx - x0f, wy = gy - y0f;
    int x0 = (int)x0f, y0 = (int)y0f;
    int x1 = x0 + 1,   y1 = y0 + 1;

    bool i00 = (x0 >= 0 && x0 < WO && y0 >= 0 && y0 < HO);
    bool i01 = (x1 >= 0 && x1 < WO && y0 >= 0 && y0 < HO);
    bool i10 = (x0 >= 0 && x0 < WO && y1 >= 0 && y1 < HO);
    bool i11 = (x1 >= 0 && x1 < WO && y1 >= 0 && y1 < HO);
    int x0c = min(max(x0, 0), WO - 1), x1c = min(max(x1, 0), WO - 1);
    int y0c = min(max(y0, 0), HO - 1), y1c = min(max(y1, 0), HO - 1);

    Bilin r;
    r.w0 = i00 ? (1.f - wx) * (1.f - wy) : 0.f;
    r.w1 = i01 ? wx * (1.f - wy)         : 0.f;
    r.w2 = i10 ? (1.f - wx) * wy         : 0.f;
    r.w3 = i11 ? wx * wy                 : 0.f;
    const float* base = g_fmap + (size_t)b * HWO * COUT;
    r.p0 = base + (size_t)(y0c * WO + x0c) * COUT;
    r.p1 = base + (size_t)(y0c * WO + x1c) * COUT;
    r.p2 = base + (size_t)(y1c * WO + x0c) * COUT;
    r.p3 = base + (size_t)(y1c * WO + x1c) * COUT;
    return r;
}

// ---------------- kernel 7: gather output + fold in g_feat zeroing -----------
__global__ void __launch_bounds__(320) k_gather(const float* __restrict__ pos,
                                                float* __restrict__ out) {
    {
        int zi = blockIdx.x * 320 + threadIdx.x;
        const int n4 = (Bq * HW * CPAD) / 4;
        if (zi < n4)
            reinterpret_cast<float4*>(g_feat)[zi] = make_float4(0.f, 0.f, 0.f, 0.f);
    }

    int tok = blockIdx.x;
    int b = tok / NOUT, j = tok % NOUT;
    int n = (j < NG) ? j : (NG + g_idx[b * SEL + (j - NG)]);

    float p0 = pos[((size_t)b * NTOK + n) * 2 + 0];
    float p1 = pos[((size_t)b * NTOK + n) * 2 + 1];
    Bilin bl = bilin_setup(b, p0, p1);

    int c = threadIdx.x;
    float xc = bl.w0 * bl.p0[c] + bl.w1 * bl.p1[c]
             + bl.w2 * bl.p2[c] + bl.w3 * bl.p3[c];
    out[(size_t)tok * COUT + c] = xc;

    if (c < 2) {
        float* po = out + (size_t)Bq * NOUT * COUT + (size_t)tok * 2;
        po[c] = (c == 0) ? p0 : p1;
    }
}

// ---------------- launcher ----------------------------------------------------
extern "C" void kernel_launch(void* const* d_in, const int* in_sizes, int n_in,
                              void* d_out, int out_size) {
    const float* x      = (const float*)d_in[0];
    const float* pos    = (const float*)d_in[1];
    const float* conv_w = (const float*)d_in[2];
    const float* conv_b = (const float*)d_in[3];
    const float* ln_g   = (const float*)d_in[4];
    const float* ln_b   = (const float*)d_in[5];
    const float* conf_w = (const float*)d_in[6];
    const float* conf_b = (const float*)d_in[7];
    const float* noise  = (const float*)d_in[8];
    float* out = (float*)d_out;

    // precondition: g_feat is zero (module-load init on first call; gather re-zeros)
    k_scatter<<<(Bq * NTOK + 7) / 8, 256>>>(x, pos, conv_w);  // #1 (float4 atomics)
    k_blurhn<<<Bq * Hh, 256>>>();                             // #2
    k_blurv<<<Bq * Hh, 256>>>();                              // #3
    k_zip<<<Bq * ZH, 256>>>();                                // #4

    dim3 cgrid(COUT / 64, HO / 4, Bq);                        // (5, 7, 32)
    k_conv<<<cgrid, 128>>>(conv_b);                           // #5

    {
        dim3 ggrid(29 * 29, Bq);
        k_gram<<<ggrid, 320>>>(ln_g, ln_b, conf_w);           // #6 (+pix fold)
    }
    k_conf<<<(Bq * NA + 255) / 256, 256>>>(pos, conf_b, noise); // #7
    k_sort<<<Bq, 1024>>>();                                   // #8
    k_gather<<<Bq * NOUT, 320>>>(pos, out);                   // #9 (+zero fold)
}